// round 15
// baseline (speedup 1.0000x reference)
#include <cuda_runtime.h>
#include <cstdint>

#define NN 50000
#define NR 500
#define NE 800000
#define DD 128

// ---- scratch (static device globals; no runtime allocation) ----
__device__ float g_aT[(size_t)128 * 384]; // g_aT[k*384+p] = a[(p&127)*384 + (p>>7)*128 + k]
__device__ float g_hs[(size_t)NN * DD];   // ent @ a_src^T
__device__ float g_hd[(size_t)NN * DD];   // ent @ a_dst^T
__device__ float g_hr[(size_t)NR * DD];   // rel @ a_rel^T
__device__ float g_ssrc[NN];
__device__ float g_sdst[NN];
__device__ float g_srel[NR];
// CSR build. INVARIANT: g_cnt == 0 at kernel_launch entry (zero-init at load;
// scanC resets it after consuming). start has a sentinel start[NN] = NE.
__device__ int   g_cnt[NN];
__device__ int   g_start[NN + 1];
__device__ int   g_cursor[NN];
__device__ int   g_part[256];             // per-chunk partial sums (196 used)
__device__ int   g_pack[NE];              // (col<<9)|rel, sorted by row

#define NCHUNK ((NN + 255) / 256)         // 196

// ---- packed f32x2 helpers (Blackwell FFMA2: 2x fp32 FMA per fma-pipe slot) ----
__device__ __forceinline__ void ffma2(unsigned long long& c, unsigned long long a,
                                      unsigned long long b) {
    asm("fma.rn.f32x2 %0, %1, %2, %3;" : "=l"(c) : "l"(a), "l"(b), "l"(c));
}
__device__ __forceinline__ unsigned long long pack2(float x) {
    unsigned long long r;
    asm("mov.b64 %0, {%1, %1};" : "=l"(r) : "f"(x));
    return r;
}
__device__ __forceinline__ float2 unpack2(unsigned long long v) {
    float2 f;
    asm("mov.b64 {%0, %1}, %2;" : "=f"(f.x), "=f"(f.y) : "l"(v));
    return f;
}

// ---- cp.async helpers ----
__device__ __forceinline__ void cp_async16(void* smem_dst, const void* gsrc) {
    uint32_t sa = (uint32_t)__cvta_generic_to_shared(smem_dst);
    asm volatile("cp.async.ca.shared.global [%0], [%1], 16;" :: "r"(sa), "l"(gsrc));
}
#define CP_COMMIT() asm volatile("cp.async.commit_group;" ::: "memory")
#define CP_WAIT1()  asm volatile("cp.async.wait_group 1;" ::: "memory")
#define CP_WAIT0()  asm volatile("cp.async.wait_group 0;" ::: "memory")

// ---- transpose a: aT[k*384+p], p<128 src, [128,256) dst ----
__global__ void transpose_a_kernel(const float* __restrict__ a) {
    int i = blockIdx.x * blockDim.x + threadIdx.x;   // i = p*128 + k
    if (i >= 128 * 384) return;
    int k = i & 127;
    int p = i >> 7;
    g_aT[k * 384 + p] = a[(p & 127) * 384 + (p >> 7) * 128 + k];
}

// ---- CSR build: histogram of destination rows (vectorized streaming reads) ----
__global__ void hist_kernel(const int* __restrict__ el) {
    int q = blockIdx.x * blockDim.x + threadIdx.x;   // one int4 = 4 edges
    if (q * 4 >= NE) return;
    int4 v = __ldcs((const int4*)el + q);
    atomicAdd(&g_cnt[v.x], 1);
    atomicAdd(&g_cnt[v.y], 1);
    atomicAdd(&g_cnt[v.z], 1);
    atomicAdd(&g_cnt[v.w], 1);
}

// ---- scan phase A: per-chunk (256 rows) sums ----
__global__ void scanA_kernel() {
    __shared__ int sh[256];
    int i = blockIdx.x * 256 + threadIdx.x;
    sh[threadIdx.x] = (i < NN) ? g_cnt[i] : 0;
    __syncthreads();
#pragma unroll
    for (int s = 128; s > 0; s >>= 1) {
        if (threadIdx.x < s) sh[threadIdx.x] += sh[threadIdx.x + s];
        __syncthreads();
    }
    if (threadIdx.x == 0) g_part[blockIdx.x] = sh[0];
}

// ---- scan phase B: exclusive scan of chunk sums (parallel, one block) ----
__global__ void scanB_kernel() {
    __shared__ int sh[256];
    int t = threadIdx.x;
    int v = (t < NCHUNK) ? g_part[t] : 0;
    sh[t] = v;
    __syncthreads();
#pragma unroll
    for (int s = 1; s < 256; s <<= 1) {
        int add = (t >= s) ? sh[t - s] : 0;
        __syncthreads();
        sh[t] += add;
        __syncthreads();
    }
    if (t < NCHUNK) g_part[t] = sh[t] - v;   // exclusive
    if (t == 0) g_start[NN] = NE;            // sentinel
}

// ---- scan phase C: per-chunk exclusive scan + base; init start & cursor.
//      Also resets g_cnt to maintain the entry invariant for the next call. ----
__global__ void scanC_kernel() {
    __shared__ int sh[256];
    int i = blockIdx.x * 256 + threadIdx.x;
    int v = (i < NN) ? g_cnt[i] : 0;
    sh[threadIdx.x] = v;
    __syncthreads();
#pragma unroll
    for (int s = 1; s < 256; s <<= 1) {
        int add = (threadIdx.x >= s) ? sh[threadIdx.x - s] : 0;
        __syncthreads();
        sh[threadIdx.x] += add;
        __syncthreads();
    }
    if (i < NN) {
        int excl = sh[threadIdx.x] - v + g_part[blockIdx.x];
        g_start[i] = excl;
        g_cursor[i] = excl;
        g_cnt[i] = 0;
    }
}

// ---- scatter edges; pack (col<<9)|rel; streaming stores (read once later) ----
__global__ void scatter_kernel(const int* __restrict__ el,
                               const int* __restrict__ rl) {
    int e = blockIdx.x * blockDim.x + threadIdx.x;
    if (e >= NE) return;
    int row = el[e];
    int col = el[NE + e];
    int r   = rl[e];
    int pos = atomicAdd(&g_cursor[row], 1);
    __stcs(&g_pack[pos], (col << 9) | r);
}

// ---- hs/hd projection + fused scores: cp.async double-buffered FFMA2 GEMM ----
// C[50000 x 256] = ent * aT[:,0:256]; BM=64, BN=256, BK=16, 2-stage pipeline.
__global__ __launch_bounds__(256) void proj_ent_kernel(
    const float* __restrict__ ent, const float* __restrict__ aT,
    const float* __restrict__ a2)
{
    __shared__ float sEm[2][64][16];    // ent tile, row-major (cp.async friendly)
    __shared__ float sA[2][16][256];    // aT tile
    int tid = threadIdx.x;
    int tr = tid >> 5;       // 0..7 (warp)
    int tc = tid & 31;       // 0..31 (lane)
    int row0 = blockIdx.x * 64;

    int mld  = tid >> 2;             // 0..63 ent row this thread loads
    int kqld = (tid & 3) * 4;        // k quadrant
    int gmld = row0 + mld;
    if (gmld > NN - 1) gmld = NN - 1;   // clamp (values unused; keeps addr legal)
    const float* ent_src = ent + (size_t)gmld * DD + kqld;

    unsigned long long acc2[8][4];
#pragma unroll
    for (int i = 0; i < 8; i++)
#pragma unroll
        for (int p = 0; p < 4; p++) acc2[i][p] = 0ull;

    // tile loader: k0 = tile base in K
    auto load_tiles = [&](int k0, int buf) {
        cp_async16(&sEm[buf][mld][kqld], ent_src + k0);
#pragma unroll
        for (int s = 0; s < 4; s++) {
            int idx = tid + s * 256;       // 0..1023
            int k   = idx >> 6;            // 0..15
            int c16 = idx & 63;            // 16B chunk within 256-float row
            cp_async16(&sA[buf][k][c16 * 4], aT + (k0 + k) * 384 + c16 * 4);
        }
        CP_COMMIT();
    };

    load_tiles(0, 0);                      // g0
#pragma unroll
    for (int it = 0; it < 8; it++) {
        int buf = it & 1;
        __syncthreads();                   // prev compute on buf^1 done -> safe to overwrite
        if (it < 7) {
            load_tiles(16 * (it + 1), buf ^ 1);
            CP_WAIT1();                    // group for `buf` has landed
        } else {
            CP_WAIT0();
        }
        __syncthreads();                   // tile `buf` visible to all warps
#pragma unroll
        for (int kk = 0; kk < 16; kk++) {
            unsigned long long e2[8];
#pragma unroll
            for (int i = 0; i < 8; i++)
                e2[i] = pack2(sEm[buf][tr * 8 + i][kk]);   // broadcast LDS.32
            const unsigned long long* pb0 =
                (const unsigned long long*)&sA[buf][kk][tc * 4];
            const unsigned long long* pb1 =
                (const unsigned long long*)&sA[buf][kk][128 + tc * 4];
            unsigned long long b2[4] = {pb0[0], pb0[1], pb1[0], pb1[1]};
#pragma unroll
            for (int i = 0; i < 8; i++)
#pragma unroll
                for (int p = 0; p < 4; p++) ffma2(acc2[i][p], e2[i], b2[p]);
        }
    }

    float4 av = *(const float4*)(a2 + tc * 4);
#pragma unroll
    for (int i = 0; i < 8; i++) {
        float2 h0 = unpack2(acc2[i][0]);
        float2 h1 = unpack2(acc2[i][1]);
        float2 d0 = unpack2(acc2[i][2]);
        float2 d1 = unpack2(acc2[i][3]);
        float ps = h0.x * av.x + h0.y * av.y + h1.x * av.z + h1.y * av.w;
        float pd = d0.x * av.x + d0.y * av.y + d1.x * av.z + d1.y * av.w;
#pragma unroll
        for (int off = 16; off > 0; off >>= 1) {
            ps += __shfl_xor_sync(0xffffffffu, ps, off);
            pd += __shfl_xor_sync(0xffffffffu, pd, off);
        }
        int gm = row0 + tr * 8 + i;
        if (gm < NN) {
            float4 o0 = make_float4(h0.x, h0.y, h1.x, h1.y);
            float4 o1 = make_float4(d0.x, d0.y, d1.x, d1.y);
            *(float4*)(g_hs + (size_t)gm * DD + tc * 4) = o0;
            *(float4*)(g_hd + (size_t)gm * DD + tc * 4) = o1;
            if (tc == 0) { g_ssrc[gm] = ps; g_sdst[gm] = pd; }
        }
    }
}

// ---- rel side: reads raw `a` directly (no transpose dependency) ----
__global__ __launch_bounds__(128) void proj_rel_kernel(
    const float* __restrict__ rel, const float* __restrict__ a,
    const float* __restrict__ a2, const float* __restrict__ Wr,
    float* __restrict__ out_rel)
{
    __shared__ float sR[4][DD];
    __shared__ float red[4][DD];
    int j = threadIdx.x;
    int i0 = blockIdx.x * 4;
#pragma unroll
    for (int r = 0; r < 4; r++) sR[r][j] = rel[(i0 + r) * DD + j];
    __syncthreads();
    float aH[4] = {0.f, 0.f, 0.f, 0.f};
    float aW[4] = {0.f, 0.f, 0.f, 0.f};
    const float* arow = a + j * 384 + 256;   // a[j, 256+k], k contiguous
#pragma unroll 4
    for (int k = 0; k < DD; k++) {
        float ak = arow[k];
        float wk = Wr[k * DD + j];
#pragma unroll
        for (int r = 0; r < 4; r++) {
            float rv = sR[r][k];
            aH[r] += rv * ak;
            aW[r] += rv * wk;
        }
    }
    float a2j = a2[j];
#pragma unroll
    for (int r = 0; r < 4; r++) {
        g_hr[(i0 + r) * DD + j] = aH[r];
        out_rel[(i0 + r) * DD + j] = fmaxf(aW[r], 0.f) + sR[r][j];
        red[r][j] = aH[r] * a2j;
    }
    __syncthreads();
#pragma unroll
    for (int s = 64; s > 0; s >>= 1) {
        if (j < s) {
#pragma unroll
            for (int r = 0; r < 4; r++) red[r][j] += red[r][j + s];
        }
        __syncthreads();
    }
    if (j < 4) g_srel[i0 + j] = red[j][0];
}

// ---- row gather: one warp per row; pk prefetch pipeline; streaming pack reads ----
// out_ent[row] = relu( (rs*hs[row] + sum_e ee*(hd[col]+hr[rel])) / (rs+eps) )
__global__ __launch_bounds__(256) void row_kernel(float* __restrict__ out) {
    int row = (blockIdx.x * blockDim.x + threadIdx.x) >> 5;
    int lane = threadIdx.x & 31;
    if (row >= NN) return;
    int beg = g_start[row];
    int end = g_start[row + 1];
    float ssrc_r = g_ssrc[row];
    float4 acc = make_float4(0.f, 0.f, 0.f, 0.f);
    float rs = 0.f;
    int pk_next = (beg < end) ? __ldcs(&g_pack[beg]) : 0;
    for (int t = beg; t < end; t++) {
        int pk = pk_next;
        if (t + 1 < end) pk_next = __ldcs(&g_pack[t + 1]);
        int col = pk >> 9;
        int r   = pk & 511;
        float x = ssrc_r + g_sdst[col] + g_srel[r];
        float p = (x > 0.f) ? -x : (-0.2f * x);     // -leaky_relu(x, 0.2)
        float ee = __expf(p);
        float4 v = *(const float4*)(g_hd + (size_t)col * DD + lane * 4);
        float4 w = *(const float4*)(g_hr + (size_t)r * DD + lane * 4);
        acc.x += ee * (v.x + w.x);
        acc.y += ee * (v.y + w.y);
        acc.z += ee * (v.z + w.z);
        acc.w += ee * (v.w + w.w);
        rs += ee;
    }
    float inv = 1.f / (rs + 1e-12f);
    float4 h = *(const float4*)(g_hs + (size_t)row * DD + lane * 4);
    float4 o;
    o.x = fmaxf((rs * h.x + acc.x) * inv, 0.f);
    o.y = fmaxf((rs * h.y + acc.y) * inv, 0.f);
    o.z = fmaxf((rs * h.z + acc.z) * inv, 0.f);
    o.w = fmaxf((rs * h.w + acc.w) * inv, 0.f);
    *(float4*)(out + (size_t)row * DD + lane * 4) = o;
}

// ---- persistent host-side handles (created once, first call = correctness
// run, before the harness's pre-capture baseline; reused every call) ----
static cudaStream_t s2 = nullptr, s3 = nullptr;
static cudaEvent_t evFork = nullptr, evJoin2 = nullptr, evJoin3 = nullptr;

extern "C" void kernel_launch(void* const* d_in, const int* in_sizes, int n_in,
                              void* d_out, int out_size)
{
    const float* ent = (const float*)d_in[0];   // 50000*128 f32
    const float* rel = (const float*)d_in[1];   // 500*128 f32
    const int*   el  = (const int*)d_in[2];     // 2*800000 int32 (jax demotes int64)
    const int*   rl  = (const int*)d_in[3];     // 800000 int32
    const float* a   = (const float*)d_in[4];   // 128*384 f32
    const float* a2  = (const float*)d_in[5];   // 128 f32
    const float* Wr  = (const float*)d_in[6];   // 128*128 f32
    float* out_ent = (float*)d_out;
    float* out_rel = out_ent + (size_t)NN * DD;

    float* aT;
    cudaGetSymbolAddress((void**)&aT, g_aT);

    if (s2 == nullptr) {
        cudaStreamCreateWithFlags(&s2, cudaStreamNonBlocking);
        cudaStreamCreateWithFlags(&s3, cudaStreamNonBlocking);
        cudaEventCreateWithFlags(&evFork, cudaEventDisableTiming);
        cudaEventCreateWithFlags(&evJoin2, cudaEventDisableTiming);
        cudaEventCreateWithFlags(&evJoin3, cudaEventDisableTiming);
    }

    // Fork (deps via events; host issue order keeps proj_ent at profiled slot #4).
    cudaEventRecord(evFork, 0);
    cudaStreamWaitEvent(s2, evFork, 0);
    cudaStreamWaitEvent(s3, evFork, 0);

    transpose_a_kernel<<<(128 * 384 + 255) / 256, 256>>>(a);            // #1 main
    hist_kernel<<<(NE / 4 + 255) / 256, 256, 0, s2>>>(el);              // #2 s2
    scanA_kernel<<<NCHUNK, 256, 0, s2>>>();                             // #3 s2
    proj_ent_kernel<<<(NN + 63) / 64, 256>>>(ent, aT, a2);              // #4 main (profiled)
    scanB_kernel<<<1, 256, 0, s2>>>();                                  // #5 s2
    scanC_kernel<<<NCHUNK, 256, 0, s2>>>();                             // #6 s2
    scatter_kernel<<<(NE + 255) / 256, 256, 0, s2>>>(el, rl);           // #7 s2
    cudaEventRecord(evJoin2, s2);
    proj_rel_kernel<<<NR / 4, 128, 0, s3>>>(rel, a, a2, Wr, out_rel);   // #8 s3
    cudaEventRecord(evJoin3, s3);

    // Join, then fused gather + epilogue
    cudaStreamWaitEvent(0, evJoin2, 0);
    cudaStreamWaitEvent(0, evJoin3, 0);
    row_kernel<<<(NN * 32 + 255) / 256, 256>>>(out_ent);                // #9 main
}

// round 16
// speedup vs baseline: 1.0408x; 1.0408x over previous
#include <cuda_runtime.h>
#include <cstdint>

#define NN 50000
#define NR 500
#define NE 800000
#define DD 128

// ---- scratch (static device globals; no runtime allocation) ----
__device__ float g_aT[(size_t)128 * 384]; // g_aT[k*384+p] = a[(p&127)*384 + (p>>7)*128 + k]
__device__ float g_hs[(size_t)NN * DD];   // ent @ a_src^T
__device__ float g_hd[(size_t)NN * DD];   // ent @ a_dst^T
__device__ float g_hr[(size_t)NR * DD];   // rel @ a_rel^T
__device__ float g_ssrc[NN];
__device__ float g_sdst[NN];
__device__ float g_srel[NR];
// CSR build. INVARIANT: g_cnt == 0 at kernel_launch entry (zero-init at load;
// scanC resets it after consuming). start has a sentinel start[NN] = NE.
__device__ int   g_cnt[NN];
__device__ int   g_start[NN + 1];
__device__ int   g_cursor[NN];
__device__ int   g_part[256];             // per-chunk partial sums (196 used)
__device__ int   g_pack[NE];              // (col<<9)|rel, sorted by row

#define NCHUNK ((NN + 255) / 256)         // 196

// ---- packed f32x2 helpers (Blackwell FFMA2: 2x fp32 FMA per fma-pipe slot) ----
__device__ __forceinline__ void ffma2(unsigned long long& c, unsigned long long a,
                                      unsigned long long b) {
    asm("fma.rn.f32x2 %0, %1, %2, %3;" : "=l"(c) : "l"(a), "l"(b), "l"(c));
}
__device__ __forceinline__ unsigned long long pack2(float x) {
    unsigned long long r;
    asm("mov.b64 %0, {%1, %1};" : "=l"(r) : "f"(x));
    return r;
}
__device__ __forceinline__ float2 unpack2(unsigned long long v) {
    float2 f;
    asm("mov.b64 {%0, %1}, %2;" : "=f"(f.x), "=f"(f.y) : "l"(v));
    return f;
}

// ---- cp.async helpers ----
__device__ __forceinline__ void cp_async16(void* smem_dst, const void* gsrc) {
    uint32_t sa = (uint32_t)__cvta_generic_to_shared(smem_dst);
    asm volatile("cp.async.ca.shared.global [%0], [%1], 16;" :: "r"(sa), "l"(gsrc));
}
#define CP_COMMIT() asm volatile("cp.async.commit_group;" ::: "memory")
#define CP_WAIT1()  asm volatile("cp.async.wait_group 1;" ::: "memory")
#define CP_WAIT0()  asm volatile("cp.async.wait_group 0;" ::: "memory")

// ---- transpose a: aT[k*384+p], p<128 src, [128,256) dst ----
__global__ void transpose_a_kernel(const float* __restrict__ a) {
    int i = blockIdx.x * blockDim.x + threadIdx.x;   // i = p*128 + k
    if (i >= 128 * 384) return;
    int k = i & 127;
    int p = i >> 7;
    g_aT[k * 384 + p] = a[(p & 127) * 384 + (p >> 7) * 128 + k];
}

// ---- CSR build: histogram of destination rows (vectorized streaming reads) ----
__global__ void hist_kernel(const int* __restrict__ el) {
    int q = blockIdx.x * blockDim.x + threadIdx.x;   // one int4 = 4 edges
    if (q * 4 >= NE) return;
    int4 v = __ldcs((const int4*)el + q);
    atomicAdd(&g_cnt[v.x], 1);
    atomicAdd(&g_cnt[v.y], 1);
    atomicAdd(&g_cnt[v.z], 1);
    atomicAdd(&g_cnt[v.w], 1);
}

// ---- scan phase A: per-chunk (256 rows) sums ----
__global__ void scanA_kernel() {
    __shared__ int sh[256];
    int i = blockIdx.x * 256 + threadIdx.x;
    sh[threadIdx.x] = (i < NN) ? g_cnt[i] : 0;
    __syncthreads();
#pragma unroll
    for (int s = 128; s > 0; s >>= 1) {
        if (threadIdx.x < s) sh[threadIdx.x] += sh[threadIdx.x + s];
        __syncthreads();
    }
    if (threadIdx.x == 0) g_part[blockIdx.x] = sh[0];
}

// ---- scan phase B: exclusive scan of chunk sums (parallel, one block) ----
__global__ void scanB_kernel() {
    __shared__ int sh[256];
    int t = threadIdx.x;
    int v = (t < NCHUNK) ? g_part[t] : 0;
    sh[t] = v;
    __syncthreads();
#pragma unroll
    for (int s = 1; s < 256; s <<= 1) {
        int add = (t >= s) ? sh[t - s] : 0;
        __syncthreads();
        sh[t] += add;
        __syncthreads();
    }
    if (t < NCHUNK) g_part[t] = sh[t] - v;   // exclusive
    if (t == 0) g_start[NN] = NE;            // sentinel
}

// ---- scan phase C: per-chunk exclusive scan + base; init start & cursor.
//      Also resets g_cnt to maintain the entry invariant for the next call. ----
__global__ void scanC_kernel() {
    __shared__ int sh[256];
    int i = blockIdx.x * 256 + threadIdx.x;
    int v = (i < NN) ? g_cnt[i] : 0;
    sh[threadIdx.x] = v;
    __syncthreads();
#pragma unroll
    for (int s = 1; s < 256; s <<= 1) {
        int add = (threadIdx.x >= s) ? sh[threadIdx.x - s] : 0;
        __syncthreads();
        sh[threadIdx.x] += add;
        __syncthreads();
    }
    if (i < NN) {
        int excl = sh[threadIdx.x] - v + g_part[blockIdx.x];
        g_start[i] = excl;
        g_cursor[i] = excl;
        g_cnt[i] = 0;
    }
}

// ---- scatter edges; pack (col<<9)|rel; streaming stores (read once later) ----
__global__ void scatter_kernel(const int* __restrict__ el,
                               const int* __restrict__ rl) {
    int e = blockIdx.x * blockDim.x + threadIdx.x;
    if (e >= NE) return;
    int row = el[e];
    int col = el[NE + e];
    int r   = rl[e];
    int pos = atomicAdd(&g_cursor[row], 1);
    __stcs(&g_pack[pos], (col << 9) | r);
}

// ---- hs/hd projection + fused scores: cp.async double-buffered FFMA2 GEMM ----
// BM=64, BN=256, BK=16, 2-stage pipeline. __launch_bounds__(256,2) pins regs
// <=128 so 2 CTAs/SM co-reside (R15 lesson: 140 regs -> 1 CTA/SM regression).
__global__ __launch_bounds__(256, 2) void proj_ent_kernel(
    const float* __restrict__ ent, const float* __restrict__ aT,
    const float* __restrict__ a2)
{
    __shared__ float sEm[2][64][16];    // ent tile, row-major (cp.async friendly)
    __shared__ float sA[2][16][256];    // aT tile
    int tid = threadIdx.x;
    int tr = tid >> 5;       // 0..7 (warp)
    int tc = tid & 31;       // 0..31 (lane)
    int row0 = blockIdx.x * 64;

    int mld  = tid >> 2;             // 0..63 ent row this thread loads
    int kqld = (tid & 3) * 4;        // k quadrant
    int gmld = row0 + mld;
    if (gmld > NN - 1) gmld = NN - 1;   // clamp (values unused; keeps addr legal)
    const float* ent_src = ent + (size_t)gmld * DD + kqld;
    // aT loader coords (2 chunks of 16B per thread per half: 4×256 B16-chunks total)
    int akA = tid >> 6;              // base k row 0..3
    int acA = (tid & 63) * 4;        // float offset within 256-row

#define LOAD_TILES(k0, buf)                                                   \
    do {                                                                      \
        cp_async16(&sEm[buf][mld][kqld], ent_src + (k0));                     \
        _Pragma("unroll")                                                     \
        for (int s = 0; s < 4; s++)                                           \
            cp_async16(&sA[buf][akA + s * 4][acA], aT + (k0 + akA + s * 4) * 384 + acA); \
        CP_COMMIT();                                                          \
    } while (0)

    unsigned long long acc2[8][4];
#pragma unroll
    for (int i = 0; i < 8; i++)
#pragma unroll
        for (int p = 0; p < 4; p++) acc2[i][p] = 0ull;

    LOAD_TILES(0, 0);
#pragma unroll 1
    for (int it = 0; it < 8; it++) {
        int buf = it & 1;
        __syncthreads();               // prev compute on buf^1 done -> safe overwrite
        if (it < 7) {
            LOAD_TILES(16 * (it + 1), buf ^ 1);
            CP_WAIT1();                // group for `buf` has landed
        } else {
            CP_WAIT0();
        }
        __syncthreads();               // tile `buf` visible to all warps
#pragma unroll
        for (int kk = 0; kk < 16; kk++) {
            unsigned long long e2[8];
#pragma unroll
            for (int i = 0; i < 8; i++)
                e2[i] = pack2(sEm[buf][tr * 8 + i][kk]);   // broadcast LDS.32
            const unsigned long long* pb0 =
                (const unsigned long long*)&sA[buf][kk][tc * 4];
            const unsigned long long* pb1 =
                (const unsigned long long*)&sA[buf][kk][128 + tc * 4];
            unsigned long long b2[4] = {pb0[0], pb0[1], pb1[0], pb1[1]};
#pragma unroll
            for (int i = 0; i < 8; i++)
#pragma unroll
                for (int p = 0; p < 4; p++) ffma2(acc2[i][p], e2[i], b2[p]);
        }
    }
#undef LOAD_TILES

    float4 av = *(const float4*)(a2 + tc * 4);
#pragma unroll
    for (int i = 0; i < 8; i++) {
        float2 h0 = unpack2(acc2[i][0]);
        float2 h1 = unpack2(acc2[i][1]);
        float2 d0 = unpack2(acc2[i][2]);
        float2 d1 = unpack2(acc2[i][3]);
        float ps = h0.x * av.x + h0.y * av.y + h1.x * av.z + h1.y * av.w;
        float pd = d0.x * av.x + d0.y * av.y + d1.x * av.z + d1.y * av.w;
#pragma unroll
        for (int off = 16; off > 0; off >>= 1) {
            ps += __shfl_xor_sync(0xffffffffu, ps, off);
            pd += __shfl_xor_sync(0xffffffffu, pd, off);
        }
        int gm = row0 + tr * 8 + i;
        if (gm < NN) {
            float4 o0 = make_float4(h0.x, h0.y, h1.x, h1.y);
            float4 o1 = make_float4(d0.x, d0.y, d1.x, d1.y);
            *(float4*)(g_hs + (size_t)gm * DD + tc * 4) = o0;
            *(float4*)(g_hd + (size_t)gm * DD + tc * 4) = o1;
            if (tc == 0) { g_ssrc[gm] = ps; g_sdst[gm] = pd; }
        }
    }
}

// ---- rel side: reads raw `a` directly (no transpose dependency) ----
__global__ __launch_bounds__(128) void proj_rel_kernel(
    const float* __restrict__ rel, const float* __restrict__ a,
    const float* __restrict__ a2, const float* __restrict__ Wr,
    float* __restrict__ out_rel)
{
    __shared__ float sR[4][DD];
    __shared__ float red[4][DD];
    int j = threadIdx.x;
    int i0 = blockIdx.x * 4;
#pragma unroll
    for (int r = 0; r < 4; r++) sR[r][j] = rel[(i0 + r) * DD + j];
    __syncthreads();
    float aH[4] = {0.f, 0.f, 0.f, 0.f};
    float aW[4] = {0.f, 0.f, 0.f, 0.f};
    const float* arow = a + j * 384 + 256;   // a[j, 256+k], k contiguous
#pragma unroll 4
    for (int k = 0; k < DD; k++) {
        float ak = arow[k];
        float wk = Wr[k * DD + j];
#pragma unroll
        for (int r = 0; r < 4; r++) {
            float rv = sR[r][k];
            aH[r] += rv * ak;
            aW[r] += rv * wk;
        }
    }
    float a2j = a2[j];
#pragma unroll
    for (int r = 0; r < 4; r++) {
        g_hr[(i0 + r) * DD + j] = aH[r];
        out_rel[(i0 + r) * DD + j] = fmaxf(aW[r], 0.f) + sR[r][j];
        red[r][j] = aH[r] * a2j;
    }
    __syncthreads();
#pragma unroll
    for (int s = 64; s > 0; s >>= 1) {
        if (j < s) {
#pragma unroll
            for (int r = 0; r < 4; r++) red[r][j] += red[r][j + s];
        }
        __syncthreads();
    }
    if (j < 4) g_srel[i0 + j] = red[j][0];
}

// ---- row gather: one warp per row; pk prefetch pipeline; streaming pack reads ----
// out_ent[row] = relu( (rs*hs[row] + sum_e ee*(hd[col]+hr[rel])) / (rs+eps) )
__global__ __launch_bounds__(256) void row_kernel(float* __restrict__ out) {
    int row = (blockIdx.x * blockDim.x + threadIdx.x) >> 5;
    int lane = threadIdx.x & 31;
    if (row >= NN) return;
    int beg = g_start[row];
    int end = g_start[row + 1];
    float ssrc_r = g_ssrc[row];
    float4 acc = make_float4(0.f, 0.f, 0.f, 0.f);
    float rs = 0.f;
    int pk_next = (beg < end) ? __ldcs(&g_pack[beg]) : 0;
    for (int t = beg; t < end; t++) {
        int pk = pk_next;
        if (t + 1 < end) pk_next = __ldcs(&g_pack[t + 1]);
        int col = pk >> 9;
        int r   = pk & 511;
        float x = ssrc_r + g_sdst[col] + g_srel[r];
        float p = (x > 0.f) ? -x : (-0.2f * x);     // -leaky_relu(x, 0.2)
        float ee = __expf(p);
        float4 v = *(const float4*)(g_hd + (size_t)col * DD + lane * 4);
        float4 w = *(const float4*)(g_hr + (size_t)r * DD + lane * 4);
        acc.x += ee * (v.x + w.x);
        acc.y += ee * (v.y + w.y);
        acc.z += ee * (v.z + w.z);
        acc.w += ee * (v.w + w.w);
        rs += ee;
    }
    float inv = 1.f / (rs + 1e-12f);
    float4 h = *(const float4*)(g_hs + (size_t)row * DD + lane * 4);
    float4 o;
    o.x = fmaxf((rs * h.x + acc.x) * inv, 0.f);
    o.y = fmaxf((rs * h.y + acc.y) * inv, 0.f);
    o.z = fmaxf((rs * h.z + acc.z) * inv, 0.f);
    o.w = fmaxf((rs * h.w + acc.w) * inv, 0.f);
    *(float4*)(out + (size_t)row * DD + lane * 4) = o;
}

// ---- persistent host-side handles (created once, first call = correctness
// run, before the harness's pre-capture baseline; reused every call) ----
static cudaStream_t s2 = nullptr, s3 = nullptr;
static cudaEvent_t evFork = nullptr, evJoin2 = nullptr, evJoin3 = nullptr;

extern "C" void kernel_launch(void* const* d_in, const int* in_sizes, int n_in,
                              void* d_out, int out_size)
{
    const float* ent = (const float*)d_in[0];   // 50000*128 f32
    const float* rel = (const float*)d_in[1];   // 500*128 f32
    const int*   el  = (const int*)d_in[2];     // 2*800000 int32 (jax demotes int64)
    const int*   rl  = (const int*)d_in[3];     // 800000 int32
    const float* a   = (const float*)d_in[4];   // 128*384 f32
    const float* a2  = (const float*)d_in[5];   // 128 f32
    const float* Wr  = (const float*)d_in[6];   // 128*128 f32
    float* out_ent = (float*)d_out;
    float* out_rel = out_ent + (size_t)NN * DD;

    float* aT;
    cudaGetSymbolAddress((void**)&aT, g_aT);

    if (s2 == nullptr) {
        cudaStreamCreateWithFlags(&s2, cudaStreamNonBlocking);
        cudaStreamCreateWithFlags(&s3, cudaStreamNonBlocking);
        cudaEventCreateWithFlags(&evFork, cudaEventDisableTiming);
        cudaEventCreateWithFlags(&evJoin2, cudaEventDisableTiming);
        cudaEventCreateWithFlags(&evJoin3, cudaEventDisableTiming);
    }

    // Fork (deps via events; host issue order keeps proj_ent at profiled slot #4).
    cudaEventRecord(evFork, 0);
    cudaStreamWaitEvent(s2, evFork, 0);
    cudaStreamWaitEvent(s3, evFork, 0);

    transpose_a_kernel<<<(128 * 384 + 255) / 256, 256>>>(a);            // #1 main
    hist_kernel<<<(NE / 4 + 255) / 256, 256, 0, s2>>>(el);              // #2 s2
    scanA_kernel<<<NCHUNK, 256, 0, s2>>>();                             // #3 s2
    proj_ent_kernel<<<(NN + 63) / 64, 256>>>(ent, aT, a2);              // #4 main (profiled)
    scanB_kernel<<<1, 256, 0, s2>>>();                                  // #5 s2
    scanC_kernel<<<NCHUNK, 256, 0, s2>>>();                             // #6 s2
    scatter_kernel<<<(NE + 255) / 256, 256, 0, s2>>>(el, rl);           // #7 s2
    cudaEventRecord(evJoin2, s2);
    proj_rel_kernel<<<NR / 4, 128, 0, s3>>>(rel, a, a2, Wr, out_rel);   // #8 s3
    cudaEventRecord(evJoin3, s3);

    // Join, then fused gather + epilogue
    cudaStreamWaitEvent(0, evJoin2, 0);
    cudaStreamWaitEvent(0, evJoin3, 0);
    row_kernel<<<(NN * 32 + 255) / 256, 256>>>(out_ent);                // #9 main
}